// round 2
// baseline (speedup 1.0000x reference)
#include <cuda_runtime.h>
#include <math.h>

// ---------------- problem constants ----------------
#define IMW   256
#define HWIMG 65536          // 256*256
#define BDIM  2
#define CDIM  96
#define C6    576            // 6*DIM
#define C2    192            // 2*DIM
#define CHID  255            // hidden_features
#define CHID2 510            // 2*hidden
#define HEADS 4
#define CH    48             // channels per head (192/4)
#define NF    33             // rfft bins of 64

// ---------------- scratch (static device memory; allocation-free) ----------------
__device__ float g_ln [(size_t)BDIM * CDIM  * HWIMG];
__device__ float g_h1 [(size_t)BDIM * C6    * HWIMG];
__device__ float g_h2 [(size_t)BDIM * C6    * HWIMG];
__device__ float g_att[(size_t)BDIM * C2    * HWIMG];
__device__ float g_x1 [(size_t)BDIM * CDIM  * HWIMG];
__device__ float g_f1 [(size_t)BDIM * CHID2 * HWIMG];
__device__ float g_g  [(size_t)BDIM * CHID  * HWIMG];

// ---------------- BiasFree LayerNorm ----------------
__global__ void ln_kernel(const float* __restrict__ x, const float* __restrict__ w,
                          float* __restrict__ out) {
    int pix = blockIdx.x * 256 + threadIdx.x;
    int b   = blockIdx.y;
    const float* xb = x   + (size_t)b * CDIM * HWIMG + pix;
    float*       ob = out + (size_t)b * CDIM * HWIMG + pix;
    float s = 0.f, s2 = 0.f;
    #pragma unroll 8
    for (int c = 0; c < CDIM; c++) {
        float v = xb[(size_t)c * HWIMG];
        s += v; s2 += v * v;
    }
    float mean = s * (1.0f / CDIM);
    float var  = s2 * (1.0f / CDIM) - mean * mean;
    float inv  = rsqrtf(var + 1e-5f);
    #pragma unroll 8
    for (int c = 0; c < CDIM; c++) {
        ob[(size_t)c * HWIMG] = xb[(size_t)c * HWIMG] * inv * w[c];
    }
}

// ---------------- conv1x1 SGEMM: Y[b][m][pix] = sum_k A[m][k] X[b][k][pix] (+R) ----------
// BM=64, BN=128, BK=16, 256 threads, 4x8 per thread.
template<bool RESID>
__global__ void __launch_bounds__(256) gemm_kernel(
        const float* __restrict__ A, const float* __restrict__ X,
        const float* __restrict__ R, float* __restrict__ Y, int M, int K) {
    __shared__ float As[16][64];
    __shared__ float Bs[16][128];
    int tid = threadIdx.x;
    int bn  = blockIdx.x * 128;
    int bm  = blockIdx.y * 64;
    int b   = blockIdx.z;
    const float* Xb = X + (size_t)b * K * HWIMG + bn;

    int arow = tid >> 2,  akb  = (tid & 3) * 4;
    int brow = tid >> 4,  bcol = (tid & 15) * 8;
    int ty   = tid >> 4,  tx   = tid & 15;

    float acc[4][8];
    #pragma unroll
    for (int i = 0; i < 4; i++)
        #pragma unroll
        for (int j = 0; j < 8; j++) acc[i][j] = 0.f;

    for (int k0 = 0; k0 < K; k0 += 16) {
        #pragma unroll
        for (int i = 0; i < 4; i++) {
            int m = bm + arow, kk = k0 + akb + i;
            As[akb + i][arow] = (m < M && kk < K) ? A[(size_t)m * K + kk] : 0.f;
        }
        {
            int kk = k0 + brow;
            float4 v0 = make_float4(0.f,0.f,0.f,0.f), v1 = v0;
            if (kk < K) {
                const float* p = Xb + (size_t)kk * HWIMG + bcol;
                v0 = *(const float4*)p;
                v1 = *(const float4*)(p + 4);
            }
            *(float4*)&Bs[brow][bcol]     = v0;
            *(float4*)&Bs[brow][bcol + 4] = v1;
        }
        __syncthreads();
        #pragma unroll
        for (int k = 0; k < 16; k++) {
            float4 av = *(float4*)&As[k][ty * 4];
            float4 b0 = *(float4*)&Bs[k][tx * 8];
            float4 b1 = *(float4*)&Bs[k][tx * 8 + 4];
            float aa[4] = {av.x, av.y, av.z, av.w};
            float bb[8] = {b0.x, b0.y, b0.z, b0.w, b1.x, b1.y, b1.z, b1.w};
            #pragma unroll
            for (int i = 0; i < 4; i++)
                #pragma unroll
                for (int j = 0; j < 8; j++)
                    acc[i][j] += aa[i] * bb[j];
        }
        __syncthreads();
    }

    #pragma unroll
    for (int i = 0; i < 4; i++) {
        int m = bm + ty * 4 + i;
        if (m < M) {
            size_t off = ((size_t)b * M + m) * HWIMG + bn + tx * 8;
            float4 o0 = make_float4(acc[i][0], acc[i][1], acc[i][2], acc[i][3]);
            float4 o1 = make_float4(acc[i][4], acc[i][5], acc[i][6], acc[i][7]);
            if (RESID) {
                float4 r0 = *(const float4*)(R + off);
                float4 r1 = *(const float4*)(R + off + 4);
                o0.x += r0.x; o0.y += r0.y; o0.z += r0.z; o0.w += r0.w;
                o1.x += r1.x; o1.y += r1.y; o1.z += r1.z; o1.w += r1.w;
            }
            *(float4*)(Y + off)     = o0;
            *(float4*)(Y + off + 4) = o1;
        }
    }
}

// ---------------- depthwise 3x3, zero padding ----------------
__device__ __forceinline__ float dw3(const float* __restrict__ ip,
                                     const float* __restrict__ wp, int y, int xx) {
    float s = 0.f;
    #pragma unroll
    for (int dy = -1; dy <= 1; dy++) {
        int yy = y + dy;
        if (yy < 0 || yy > 255) continue;
        #pragma unroll
        for (int dx = -1; dx <= 1; dx++) {
            int x2 = xx + dx;
            if (x2 < 0 || x2 > 255) continue;
            s += ip[yy * IMW + x2] * wp[(dy + 1) * 3 + (dx + 1)];
        }
    }
    return s;
}

__global__ void dwconv_kernel(const float* __restrict__ in, const float* __restrict__ w,
                              float* __restrict__ out, int C) {
    int pix = blockIdx.x * 256 + threadIdx.x;
    int c = blockIdx.y, b = blockIdx.z;
    int y = pix >> 8, xx = pix & 255;
    const float* ip = in + ((size_t)b * C + c) * HWIMG;
    out[((size_t)b * C + c) * HWIMG + pix] = dw3(ip, w + c * 9, y, xx);
}

// fused FFN dwconv + gelu gate: g[c] = gelu(dw(in[c])) * dw(in[c+CHID])
__global__ void dwgate_kernel(const float* __restrict__ in, const float* __restrict__ w,
                              float* __restrict__ g) {
    int pix = blockIdx.x * 256 + threadIdx.x;
    int c = blockIdx.y, b = blockIdx.z;
    int y = pix >> 8, xx = pix & 255;
    const float* ip1 = in + ((size_t)b * CHID2 + c) * HWIMG;
    const float* ip2 = in + ((size_t)b * CHID2 + CHID + c) * HWIMG;
    float v1 = dw3(ip1, w + c * 9, y, xx);
    float v2 = dw3(ip2, w + (CHID + c) * 9, y, xx);
    float ge = 0.5f * v1 * (1.f + erff(v1 * 0.70710678118654752f));
    g[((size_t)b * CHID + c) * HWIMG + pix] = ge * v2;
}

// ---------------- windowed FFT attention ----------------
// smem (floats): tab(float2 x64)=128 | sx 48x65=3120 | qf 48x33 float2=3168
//                kf/vf 3168 | at 33x33 float2=2178 | nrm 33    => 11795 floats
#define SM_TAB 0
#define SM_SX  128
#define SM_QF  3248
#define SM_KF  6416
#define SM_AT  9584
#define SM_NRM 11762
#define ATTN_SMEM_FLOATS 11795

__global__ void __launch_bounds__(256, 4) attn_kernel(
        const float* __restrict__ qkv, const float* __restrict__ temp,
        float* __restrict__ outp) {
    extern __shared__ float sm[];
    float2* tab = (float2*)(sm + SM_TAB);
    float*  sx  = sm + SM_SX;
    float2* qf  = (float2*)(sm + SM_QF);
    float2* kf  = (float2*)(sm + SM_KF);   // later reused as vf
    float2* at  = (float2*)(sm + SM_AT);
    float*  nrm = sm + SM_NRM;

    int tid  = threadIdx.x;
    int wy   = blockIdx.x >> 5, wx = blockIdx.x & 31;
    int head = blockIdx.y, b = blockIdx.z;

    if (tid < 64) {
        float s, c;
        sincosf(6.2831853071795864f * (float)tid / 64.f, &s, &c);
        tab[tid] = make_float2(c, s);
    }

    size_t base = ((size_t)b * C6 + head * CH) * HWIMG + (size_t)(wy * 8) * IMW + wx * 8;

    // --- load q window ---
    {
        const float* src = qkv + base;
        for (int i = tid; i < CH * 64; i += 256) {
            int c = i >> 6, n = i & 63;
            sx[c * 65 + n] = src[(size_t)c * HWIMG + (n >> 3) * IMW + (n & 7)];
        }
    }
    __syncthreads();

    // --- rDFT helper pattern: 4 channels x 2 freqs per thread, 204 threads ---
    #define DFT_BODY(DST) \
        if (tid < 204) { \
            int c0 = (tid / 17) * 4, f0 = (tid % 17) * 2; \
            bool has1 = (f0 + 1) < NF; \
            float r0[4] = {0,0,0,0}, i0[4] = {0,0,0,0}; \
            float r1[4] = {0,0,0,0}, i1[4] = {0,0,0,0}; \
            int idx0 = 0, idx1 = 0; \
            for (int n = 0; n < 64; n++) { \
                float2 w0 = tab[idx0], w1 = tab[idx1]; \
                _Pragma("unroll") \
                for (int j = 0; j < 4; j++) { \
                    float xv = sx[(c0 + j) * 65 + n]; \
                    r0[j] += xv * w0.x; i0[j] -= xv * w0.y; \
                    r1[j] += xv * w1.x; i1[j] -= xv * w1.y; \
                } \
                idx0 = (idx0 + f0) & 63; idx1 = (idx1 + f0 + 1) & 63; \
            } \
            _Pragma("unroll") \
            for (int j = 0; j < 4; j++) { \
                DST[(c0 + j) * NF + f0] = make_float2(r0[j], i0[j]); \
                if (has1) DST[(c0 + j) * NF + f0 + 1] = make_float2(r1[j], i1[j]); \
            } \
        }

    DFT_BODY(qf)
    __syncthreads();

    // --- load k window ---
    {
        const float* src = qkv + base + (size_t)C2 * HWIMG;
        for (int i = tid; i < CH * 64; i += 256) {
            int c = i >> 6, n = i & 63;
            sx[c * 65 + n] = src[(size_t)c * HWIMG + (n >> 3) * IMW + (n & 7)];
        }
    }
    __syncthreads();
    DFT_BODY(kf)
    __syncthreads();

    // --- gram: at[f][g] = tv * sum_c qf[c][f]*kf[c][g]; plus load v window ---
    float tv = temp[head];
    for (int e = tid; e < 17 * 17; e += 256) {
        int ft = e / 17, gt = e - ft * 17;
        int f0 = ft * 2, g0 = gt * 2;
        int f1 = (f0 + 1 < NF) ? f0 + 1 : f0;
        int g1 = (g0 + 1 < NF) ? g0 + 1 : g0;
        float2 a00 = {0,0}, a01 = {0,0}, a10 = {0,0}, a11 = {0,0};
        #pragma unroll 4
        for (int c = 0; c < CH; c++) {
            float2 q0 = qf[c * NF + f0], q1 = qf[c * NF + f1];
            float2 k0 = kf[c * NF + g0], k1 = kf[c * NF + g1];
            a00.x += q0.x*k0.x - q0.y*k0.y; a00.y += q0.x*k0.y + q0.y*k0.x;
            a01.x += q0.x*k1.x - q0.y*k1.y; a01.y += q0.x*k1.y + q0.y*k1.x;
            a10.x += q1.x*k0.x - q1.y*k0.y; a10.y += q1.x*k0.y + q1.y*k0.x;
            a11.x += q1.x*k1.x - q1.y*k1.y; a11.y += q1.x*k1.y + q1.y*k1.x;
        }
        at[f0 * NF + g0] = make_float2(a00.x * tv, a00.y * tv);
        if (g0 + 1 < NF) at[f0 * NF + g0 + 1] = make_float2(a01.x * tv, a01.y * tv);
        if (f0 + 1 < NF) {
            at[(f0 + 1) * NF + g0] = make_float2(a10.x * tv, a10.y * tv);
            if (g0 + 1 < NF) at[(f0 + 1) * NF + g0 + 1] = make_float2(a11.x * tv, a11.y * tv);
        }
    }
    {   // load v window into sx (sx free: k-DFT finished last phase)
        const float* src = qkv + base + (size_t)(2 * C2) * HWIMG;
        for (int i = tid; i < CH * 64; i += 256) {
            int c = i >> 6, n = i & 63;
            sx[c * 65 + n] = src[(size_t)c * HWIMG + (n >> 3) * IMW + (n & 7)];
        }
    }
    __syncthreads();

    // --- v DFT into kf (tid<204) + row norms (tid 204..236) ---
    DFT_BODY(kf)
    if (tid >= 204 && tid < 204 + NF) {
        int f = tid - 204;
        float s = 0.f;
        #pragma unroll
        for (int g = 0; g < NF; g++) {
            float2 a = at[f * NF + g];
            s += a.x * a.x + a.y * a.y;
        }
        nrm[f] = rsqrtf(s);
    }
    __syncthreads();

    // --- apply: qf[c][f] = (nrm[f]*wf/64) * sum_g at[f][g]*vf[c][g] ---
    if (tid < 204) {
        int c0 = (tid / 17) * 4, f0 = (tid % 17) * 2;
        bool has1 = (f0 + 1) < NF;
        int f1 = has1 ? f0 + 1 : f0;
        float2 acc0[4] = {{0,0},{0,0},{0,0},{0,0}};
        float2 acc1[4] = {{0,0},{0,0},{0,0},{0,0}};
        #pragma unroll 3
        for (int g = 0; g < NF; g++) {
            float2 a0 = at[f0 * NF + g], a1 = at[f1 * NF + g];
            #pragma unroll
            for (int j = 0; j < 4; j++) {
                float2 v = kf[(c0 + j) * NF + g];
                acc0[j].x += a0.x*v.x - a0.y*v.y; acc0[j].y += a0.x*v.y + a0.y*v.x;
                acc1[j].x += a1.x*v.x - a1.y*v.y; acc1[j].y += a1.x*v.y + a1.y*v.x;
            }
        }
        float s0 = nrm[f0] * ((f0 == 0 || f0 == 32) ? 1.f : 2.f) * (1.f / 64.f);
        float s1 = nrm[f1] * 2.f * (1.f / 64.f);   // f1 odd -> weight 2
        #pragma unroll
        for (int j = 0; j < 4; j++) {
            qf[(c0 + j) * NF + f0] = make_float2(acc0[j].x * s0, acc0[j].y * s0);
            if (has1) qf[(c0 + j) * NF + f0 + 1] = make_float2(acc1[j].x * s1, acc1[j].y * s1);
        }
    }
    __syncthreads();

    // --- irDFT (weights folded already): o[c][n] = sum_f Re(qf[c][f] e^{+i2pi f n/64}) ---
    float* outBase = outp + ((size_t)b * C2 + head * CH) * HWIMG + (size_t)(wy * 8) * IMW + wx * 8;
    if (tid < 192) {
        int c0 = (tid / 16) * 4, n0 = (tid & 15) * 4;
        float a[4][4];
        #pragma unroll
        for (int j = 0; j < 4; j++)
            #pragma unroll
            for (int jn = 0; jn < 4; jn++) a[j][jn] = 0.f;
        for (int f = 0; f < NF; f++) {
            float2 p[4];
            #pragma unroll
            for (int j = 0; j < 4; j++) p[j] = qf[(c0 + j) * NF + f];
            int idx = (f * n0) & 63;
            #pragma unroll
            for (int jn = 0; jn < 4; jn++) {
                float2 w = tab[idx];
                #pragma unroll
                for (int j = 0; j < 4; j++)
                    a[j][jn] += p[j].x * w.x - p[j].y * w.y;
                idx = (idx + f) & 63;
            }
        }
        #pragma unroll
        for (int jn = 0; jn < 4; jn++) {
            int n = n0 + jn;
            size_t poff = (size_t)(n >> 3) * IMW + (n & 7);
            #pragma unroll
            for (int j = 0; j < 4; j++)
                outBase[(size_t)(c0 + j) * HWIMG + poff] = a[j][jn];
        }
    }
}

// ---------------- launch ----------------
extern "C" void kernel_launch(void* const* d_in, const int* in_sizes, int n_in,
                              void* d_out, int out_size) {
    const float* x      = (const float*)d_in[0];
    const float* w_hid  = (const float*)d_in[1];
    const float* w_hdw  = (const float*)d_in[2];
    const float* w_proj = (const float*)d_in[3];
    const float* temp   = (const float*)d_in[4];
    const float* n1w    = (const float*)d_in[5];
    const float* n2w    = (const float*)d_in[6];
    const float* w_fin  = (const float*)d_in[7];
    const float* w_fdw  = (const float*)d_in[8];
    const float* w_fout = (const float*)d_in[9];
    float* out = (float*)d_out;

    float *ln, *h1, *h2, *att, *x1, *f1, *gg;
    cudaGetSymbolAddress((void**)&ln,  g_ln);
    cudaGetSymbolAddress((void**)&h1,  g_h1);
    cudaGetSymbolAddress((void**)&h2,  g_h2);
    cudaGetSymbolAddress((void**)&att, g_att);
    cudaGetSymbolAddress((void**)&x1,  g_x1);
    cudaGetSymbolAddress((void**)&f1,  g_f1);
    cudaGetSymbolAddress((void**)&gg,  g_g);

    cudaFuncSetAttribute(attn_kernel, cudaFuncAttributeMaxDynamicSharedMemorySize,
                         ATTN_SMEM_FLOATS * 4);

    // 1) LN1
    ln_kernel<<<dim3(256, BDIM), 256>>>(x, n1w, ln);
    // 2) to_hidden 1x1 (96 -> 576)
    gemm_kernel<false><<<dim3(512, 9, BDIM), 256>>>(w_hid, ln, nullptr, h1, C6, CDIM);
    // 3) dwconv 3x3 on 576 ch
    dwconv_kernel<<<dim3(256, C6, BDIM), 256>>>(h1, w_hdw, h2, C6);
    // 4) windowed FFT attention
    attn_kernel<<<dim3(1024, HEADS, BDIM), 256, ATTN_SMEM_FLOATS * 4>>>(h2, temp, att);
    // 5) project_out 1x1 (192 -> 96) + residual x
    gemm_kernel<true><<<dim3(512, 2, BDIM), 256>>>(w_proj, att, x, x1, CDIM, C2);
    // 6) LN2
    ln_kernel<<<dim3(256, BDIM), 256>>>(x1, n2w, ln);
    // 7) ffn in 1x1 (96 -> 510)
    gemm_kernel<false><<<dim3(512, 8, BDIM), 256>>>(w_fin, ln, nullptr, f1, CHID2, CDIM);
    // 8) fused dwconv 3x3 + gelu gate (510 ch -> 255 ch)
    dwgate_kernel<<<dim3(256, CHID, BDIM), 256>>>(f1, w_fdw, gg);
    // 9) ffn out 1x1 (255 -> 96) + residual x1 -> d_out
    gemm_kernel<true><<<dim3(512, 2, BDIM), 256>>>(w_fout, gg, x1, out, CDIM, CHID);
}

// round 3
// speedup vs baseline: 1.2794x; 1.2794x over previous
#include <cuda_runtime.h>
#include <math.h>
#include <stdint.h>

// ---------------- problem constants ----------------
#define IMW   256
#define HWIMG 65536          // 256*256
#define BDIM  2
#define CDIM  96
#define C6    576            // 6*DIM
#define C2    192            // 2*DIM
#define CHID  255            // hidden_features
#define CHID2 510            // 2*hidden
#define HEADS 4
#define CH    48             // channels per head (192/4)
#define NF    33             // rfft bins of 64

// ---------------- scratch (static device memory; allocation-free) ----------------
__device__ float g_ln [(size_t)BDIM * CDIM  * HWIMG];
__device__ float g_h1 [(size_t)BDIM * C6    * HWIMG];
__device__ float g_h2 [(size_t)BDIM * C6    * HWIMG];
__device__ float g_att[(size_t)BDIM * C2    * HWIMG];
__device__ float g_x1 [(size_t)BDIM * CDIM  * HWIMG];
__device__ float g_f1 [(size_t)BDIM * CHID2 * HWIMG];
__device__ float g_g  [(size_t)BDIM * CHID  * HWIMG];

// ---------------- BiasFree LayerNorm ----------------
__global__ void ln_kernel(const float* __restrict__ x, const float* __restrict__ w,
                          float* __restrict__ out) {
    int pix = blockIdx.x * 256 + threadIdx.x;
    int b   = blockIdx.y;
    const float* xb = x   + (size_t)b * CDIM * HWIMG + pix;
    float*       ob = out + (size_t)b * CDIM * HWIMG + pix;
    float s = 0.f, s2 = 0.f;
    #pragma unroll 8
    for (int c = 0; c < CDIM; c++) {
        float v = xb[(size_t)c * HWIMG];
        s += v; s2 += v * v;
    }
    float mean = s * (1.0f / CDIM);
    float var  = s2 * (1.0f / CDIM) - mean * mean;
    float inv  = rsqrtf(var + 1e-5f);
    #pragma unroll 8
    for (int c = 0; c < CDIM; c++) {
        ob[(size_t)c * HWIMG] = xb[(size_t)c * HWIMG] * inv * w[c];
    }
}

// ---------------- tf32 tensor-core conv1x1 GEMM ----------------
// Y[b][m][pix] = sum_k A[m][k] X[b][k][pix] (+R), tf32 inputs, fp32 accum.
// BM=128, BN=128, BK=32, 256 threads (8 warps), warp tile 64x32 (m16n8k8).
#define GBM 128
#define GBN 128
#define GBK 32
#define GPAD 8           // row stride 136 floats: 8*tg+g distinct mod 32

__device__ __forceinline__ uint32_t f2tf(float f) {
    uint32_t u;
    asm("cvt.rna.tf32.f32 %0, %1;" : "=r"(u) : "f"(f));
    return u;
}

template<bool RESID>
__global__ void __launch_bounds__(256) gemm_tf32_kernel(
        const float* __restrict__ A, const float* __restrict__ X,
        const float* __restrict__ R, float* __restrict__ Y, int M, int K) {
    __shared__ uint32_t As[GBK][GBM + GPAD];
    __shared__ uint32_t Bs[GBK][GBN + GPAD];

    int tid  = threadIdx.x;
    int warp = tid >> 5, lane = tid & 31;
    int g    = lane >> 2, tg = lane & 3;
    int wm   = (warp & 1) * 64;     // warp m offset in tile
    int wn   = (warp >> 1) * 32;    // warp n offset in tile

    int bn = blockIdx.x * GBN;
    int bm = blockIdx.y * GBM;
    int b  = blockIdx.z;
    const float* Xb = X + (size_t)b * K * HWIMG + bn;

    float acc[4][4][4];
    #pragma unroll
    for (int mt = 0; mt < 4; mt++)
        #pragma unroll
        for (int nt = 0; nt < 4; nt++)
            #pragma unroll
            for (int i = 0; i < 4; i++) acc[mt][nt][i] = 0.f;

    // X load mapping: row kk = tid>>3 (32 rows), cols (tid&7)*4 + j*32
    int xk = tid >> 3;
    int xc = (tid & 7) * 4;

    for (int k0 = 0; k0 < K; k0 += GBK) {
        // ---- load A tile (128m x 32k) ----
        #pragma unroll
        for (int i = 0; i < 16; i++) {
            int lin = tid + i * 256;
            int m = lin & 127, k = lin >> 7;
            int gm = bm + m, gk = k0 + k;
            float v = (gm < M && gk < K) ? A[(size_t)gm * K + gk] : 0.f;
            As[k][m] = f2tf(v);
        }
        // ---- load X tile (32k x 128n) ----
        {
            bool kok = (k0 + xk) < K;
            const float* p = Xb + (size_t)(k0 + xk) * HWIMG + xc;
            #pragma unroll
            for (int j = 0; j < 4; j++) {
                float4 v = kok ? *(const float4*)(p + j * 32)
                               : make_float4(0.f, 0.f, 0.f, 0.f);
                int c = xc + j * 32;
                Bs[xk][c + 0] = f2tf(v.x);
                Bs[xk][c + 1] = f2tf(v.y);
                Bs[xk][c + 2] = f2tf(v.z);
                Bs[xk][c + 3] = f2tf(v.w);
            }
        }
        __syncthreads();

        #pragma unroll
        for (int ks = 0; ks < 4; ks++) {
            int kb = ks * 8;
            uint32_t af[4][4], bf[4][2];
            #pragma unroll
            for (int mt = 0; mt < 4; mt++) {
                int m0 = wm + mt * 16;
                af[mt][0] = As[kb + tg    ][m0 + g    ];
                af[mt][1] = As[kb + tg    ][m0 + g + 8];
                af[mt][2] = As[kb + tg + 4][m0 + g    ];
                af[mt][3] = As[kb + tg + 4][m0 + g + 8];
            }
            #pragma unroll
            for (int nt = 0; nt < 4; nt++) {
                int n0 = wn + nt * 8;
                bf[nt][0] = Bs[kb + tg    ][n0 + g];
                bf[nt][1] = Bs[kb + tg + 4][n0 + g];
            }
            #pragma unroll
            for (int mt = 0; mt < 4; mt++)
                #pragma unroll
                for (int nt = 0; nt < 4; nt++) {
                    asm volatile(
                        "mma.sync.aligned.m16n8k8.row.col.f32.tf32.tf32.f32 "
                        "{%0,%1,%2,%3}, {%4,%5,%6,%7}, {%8,%9}, {%0,%1,%2,%3};\n"
                        : "+f"(acc[mt][nt][0]), "+f"(acc[mt][nt][1]),
                          "+f"(acc[mt][nt][2]), "+f"(acc[mt][nt][3])
                        : "r"(af[mt][0]), "r"(af[mt][1]),
                          "r"(af[mt][2]), "r"(af[mt][3]),
                          "r"(bf[nt][0]), "r"(bf[nt][1]));
                }
        }
        __syncthreads();
    }

    // ---- epilogue ----
    #pragma unroll
    for (int mt = 0; mt < 4; mt++) {
        int m0 = bm + wm + mt * 16 + g;
        int m1 = m0 + 8;
        #pragma unroll
        for (int nt = 0; nt < 4; nt++) {
            int n = bn + wn + nt * 8 + 2 * tg;
            if (m0 < M) {
                size_t off = ((size_t)b * M + m0) * HWIMG + n;
                float2 o = make_float2(acc[mt][nt][0], acc[mt][nt][1]);
                if (RESID) {
                    float2 r = *(const float2*)(R + off);
                    o.x += r.x; o.y += r.y;
                }
                *(float2*)(Y + off) = o;
            }
            if (m1 < M) {
                size_t off = ((size_t)b * M + m1) * HWIMG + n;
                float2 o = make_float2(acc[mt][nt][2], acc[mt][nt][3]);
                if (RESID) {
                    float2 r = *(const float2*)(R + off);
                    o.x += r.x; o.y += r.y;
                }
                *(float2*)(Y + off) = o;
            }
        }
    }
}

// ---------------- depthwise 3x3, zero padding ----------------
__device__ __forceinline__ float dw3(const float* __restrict__ ip,
                                     const float* __restrict__ wp, int y, int xx) {
    float s = 0.f;
    #pragma unroll
    for (int dy = -1; dy <= 1; dy++) {
        int yy = y + dy;
        if (yy < 0 || yy > 255) continue;
        #pragma unroll
        for (int dx = -1; dx <= 1; dx++) {
            int x2 = xx + dx;
            if (x2 < 0 || x2 > 255) continue;
            s += ip[yy * IMW + x2] * wp[(dy + 1) * 3 + (dx + 1)];
        }
    }
    return s;
}

__global__ void dwconv_kernel(const float* __restrict__ in, const float* __restrict__ w,
                              float* __restrict__ out, int C) {
    int pix = blockIdx.x * 256 + threadIdx.x;
    int c = blockIdx.y, b = blockIdx.z;
    int y = pix >> 8, xx = pix & 255;
    const float* ip = in + ((size_t)b * C + c) * HWIMG;
    out[((size_t)b * C + c) * HWIMG + pix] = dw3(ip, w + c * 9, y, xx);
}

// fused FFN dwconv + gelu gate: g[c] = gelu(dw(in[c])) * dw(in[c+CHID])
__global__ void dwgate_kernel(const float* __restrict__ in, const float* __restrict__ w,
                              float* __restrict__ g) {
    int pix = blockIdx.x * 256 + threadIdx.x;
    int c = blockIdx.y, b = blockIdx.z;
    int y = pix >> 8, xx = pix & 255;
    const float* ip1 = in + ((size_t)b * CHID2 + c) * HWIMG;
    const float* ip2 = in + ((size_t)b * CHID2 + CHID + c) * HWIMG;
    float v1 = dw3(ip1, w + c * 9, y, xx);
    float v2 = dw3(ip2, w + (CHID + c) * 9, y, xx);
    float ge = 0.5f * v1 * (1.f + erff(v1 * 0.70710678118654752f));
    g[((size_t)b * CHID + c) * HWIMG + pix] = ge * v2;
}

// ---------------- windowed FFT attention ----------------
#define SM_TAB 0
#define SM_SX  128
#define SM_QF  3248
#define SM_KF  6416
#define SM_AT  9584
#define SM_NRM 11762
#define ATTN_SMEM_FLOATS 11795

__global__ void __launch_bounds__(256, 4) attn_kernel(
        const float* __restrict__ qkv, const float* __restrict__ temp,
        float* __restrict__ outp) {
    extern __shared__ float sm[];
    float2* tab = (float2*)(sm + SM_TAB);
    float*  sx  = sm + SM_SX;
    float2* qf  = (float2*)(sm + SM_QF);
    float2* kf  = (float2*)(sm + SM_KF);   // later reused as vf
    float2* at  = (float2*)(sm + SM_AT);
    float*  nrm = sm + SM_NRM;

    int tid  = threadIdx.x;
    int wy   = blockIdx.x >> 5, wx = blockIdx.x & 31;
    int head = blockIdx.y, b = blockIdx.z;

    if (tid < 64) {
        float s, c;
        sincosf(6.2831853071795864f * (float)tid / 64.f, &s, &c);
        tab[tid] = make_float2(c, s);
    }

    size_t base = ((size_t)b * C6 + head * CH) * HWIMG + (size_t)(wy * 8) * IMW + wx * 8;

    {
        const float* src = qkv + base;
        for (int i = tid; i < CH * 64; i += 256) {
            int c = i >> 6, n = i & 63;
            sx[c * 65 + n] = src[(size_t)c * HWIMG + (n >> 3) * IMW + (n & 7)];
        }
    }
    __syncthreads();

    #define DFT_BODY(DST) \
        if (tid < 204) { \
            int c0 = (tid / 17) * 4, f0 = (tid % 17) * 2; \
            bool has1 = (f0 + 1) < NF; \
            float r0[4] = {0,0,0,0}, i0[4] = {0,0,0,0}; \
            float r1[4] = {0,0,0,0}, i1[4] = {0,0,0,0}; \
            int idx0 = 0, idx1 = 0; \
            for (int n = 0; n < 64; n++) { \
                float2 w0 = tab[idx0], w1 = tab[idx1]; \
                _Pragma("unroll") \
                for (int j = 0; j < 4; j++) { \
                    float xv = sx[(c0 + j) * 65 + n]; \
                    r0[j] += xv * w0.x; i0[j] -= xv * w0.y; \
                    r1[j] += xv * w1.x; i1[j] -= xv * w1.y; \
                } \
                idx0 = (idx0 + f0) & 63; idx1 = (idx1 + f0 + 1) & 63; \
            } \
            _Pragma("unroll") \
            for (int j = 0; j < 4; j++) { \
                DST[(c0 + j) * NF + f0] = make_float2(r0[j], i0[j]); \
                if (has1) DST[(c0 + j) * NF + f0 + 1] = make_float2(r1[j], i1[j]); \
            } \
        }

    DFT_BODY(qf)
    __syncthreads();

    {
        const float* src = qkv + base + (size_t)C2 * HWIMG;
        for (int i = tid; i < CH * 64; i += 256) {
            int c = i >> 6, n = i & 63;
            sx[c * 65 + n] = src[(size_t)c * HWIMG + (n >> 3) * IMW + (n & 7)];
        }
    }
    __syncthreads();
    DFT_BODY(kf)
    __syncthreads();

    float tv = temp[head];
    for (int e = tid; e < 17 * 17; e += 256) {
        int ft = e / 17, gt = e - ft * 17;
        int f0 = ft * 2, g0 = gt * 2;
        int f1 = (f0 + 1 < NF) ? f0 + 1 : f0;
        int g1 = (g0 + 1 < NF) ? g0 + 1 : g0;
        float2 a00 = {0,0}, a01 = {0,0}, a10 = {0,0}, a11 = {0,0};
        #pragma unroll 4
        for (int c = 0; c < CH; c++) {
            float2 q0 = qf[c * NF + f0], q1 = qf[c * NF + f1];
            float2 k0 = kf[c * NF + g0], k1 = kf[c * NF + g1];
            a00.x += q0.x*k0.x - q0.y*k0.y; a00.y += q0.x*k0.y + q0.y*k0.x;
            a01.x += q0.x*k1.x - q0.y*k1.y; a01.y += q0.x*k1.y + q0.y*k1.x;
            a10.x += q1.x*k0.x - q1.y*k0.y; a10.y += q1.x*k0.y + q1.y*k0.x;
            a11.x += q1.x*k1.x - q1.y*k1.y; a11.y += q1.x*k1.y + q1.y*k1.x;
        }
        at[f0 * NF + g0] = make_float2(a00.x * tv, a00.y * tv);
        if (g0 + 1 < NF) at[f0 * NF + g0 + 1] = make_float2(a01.x * tv, a01.y * tv);
        if (f0 + 1 < NF) {
            at[(f0 + 1) * NF + g0] = make_float2(a10.x * tv, a10.y * tv);
            if (g0 + 1 < NF) at[(f0 + 1) * NF + g0 + 1] = make_float2(a11.x * tv, a11.y * tv);
        }
    }
    {
        const float* src = qkv + base + (size_t)(2 * C2) * HWIMG;
        for (int i = tid; i < CH * 64; i += 256) {
            int c = i >> 6, n = i & 63;
            sx[c * 65 + n] = src[(size_t)c * HWIMG + (n >> 3) * IMW + (n & 7)];
        }
    }
    __syncthreads();

    DFT_BODY(kf)
    if (tid >= 204 && tid < 204 + NF) {
        int f = tid - 204;
        float s = 0.f;
        #pragma unroll
        for (int g = 0; g < NF; g++) {
            float2 a = at[f * NF + g];
            s += a.x * a.x + a.y * a.y;
        }
        nrm[f] = rsqrtf(s);
    }
    __syncthreads();

    if (tid < 204) {
        int c0 = (tid / 17) * 4, f0 = (tid % 17) * 2;
        bool has1 = (f0 + 1) < NF;
        int f1 = has1 ? f0 + 1 : f0;
        float2 acc0[4] = {{0,0},{0,0},{0,0},{0,0}};
        float2 acc1[4] = {{0,0},{0,0},{0,0},{0,0}};
        #pragma unroll 3
        for (int g = 0; g < NF; g++) {
            float2 a0 = at[f0 * NF + g], a1 = at[f1 * NF + g];
            #pragma unroll
            for (int j = 0; j < 4; j++) {
                float2 v = kf[(c0 + j) * NF + g];
                acc0[j].x += a0.x*v.x - a0.y*v.y; acc0[j].y += a0.x*v.y + a0.y*v.x;
                acc1[j].x += a1.x*v.x - a1.y*v.y; acc1[j].y += a1.x*v.y + a1.y*v.x;
            }
        }
        float s0 = nrm[f0] * ((f0 == 0 || f0 == 32) ? 1.f : 2.f) * (1.f / 64.f);
        float s1 = nrm[f1] * 2.f * (1.f / 64.f);
        #pragma unroll
        for (int j = 0; j < 4; j++) {
            qf[(c0 + j) * NF + f0] = make_float2(acc0[j].x * s0, acc0[j].y * s0);
            if (has1) qf[(c0 + j) * NF + f0 + 1] = make_float2(acc1[j].x * s1, acc1[j].y * s1);
        }
    }
    __syncthreads();

    float* outBase = outp + ((size_t)b * C2 + head * CH) * HWIMG + (size_t)(wy * 8) * IMW + wx * 8;
    if (tid < 192) {
        int c0 = (tid / 16) * 4, n0 = (tid & 15) * 4;
        float a[4][4];
        #pragma unroll
        for (int j = 0; j < 4; j++)
            #pragma unroll
            for (int jn = 0; jn < 4; jn++) a[j][jn] = 0.f;
        for (int f = 0; f < NF; f++) {
            float2 p[4];
            #pragma unroll
            for (int j = 0; j < 4; j++) p[j] = qf[(c0 + j) * NF + f];
            int idx = (f * n0) & 63;
            #pragma unroll
            for (int jn = 0; jn < 4; jn++) {
                float2 w = tab[idx];
                #pragma unroll
                for (int j = 0; j < 4; j++)
                    a[j][jn] += p[j].x * w.x - p[j].y * w.y;
                idx = (idx + f) & 63;
            }
        }
        #pragma unroll
        for (int jn = 0; jn < 4; jn++) {
            int n = n0 + jn;
            size_t poff = (size_t)(n >> 3) * IMW + (n & 7);
            #pragma unroll
            for (int j = 0; j < 4; j++)
                outBase[(size_t)(c0 + j) * HWIMG + poff] = a[j][jn];
        }
    }
}

// ---------------- launch ----------------
extern "C" void kernel_launch(void* const* d_in, const int* in_sizes, int n_in,
                              void* d_out, int out_size) {
    const float* x      = (const float*)d_in[0];
    const float* w_hid  = (const float*)d_in[1];
    const float* w_hdw  = (const float*)d_in[2];
    const float* w_proj = (const float*)d_in[3];
    const float* temp   = (const float*)d_in[4];
    const float* n1w    = (const float*)d_in[5];
    const float* n2w    = (const float*)d_in[6];
    const float* w_fin  = (const float*)d_in[7];
    const float* w_fdw  = (const float*)d_in[8];
    const float* w_fout = (const float*)d_in[9];
    float* out = (float*)d_out;

    float *ln, *h1, *h2, *att, *x1, *f1, *gg;
    cudaGetSymbolAddress((void**)&ln,  g_ln);
    cudaGetSymbolAddress((void**)&h1,  g_h1);
    cudaGetSymbolAddress((void**)&h2,  g_h2);
    cudaGetSymbolAddress((void**)&att, g_att);
    cudaGetSymbolAddress((void**)&x1,  g_x1);
    cudaGetSymbolAddress((void**)&f1,  g_f1);
    cudaGetSymbolAddress((void**)&gg,  g_g);

    cudaFuncSetAttribute(attn_kernel, cudaFuncAttributeMaxDynamicSharedMemorySize,
                         ATTN_SMEM_FLOATS * 4);

    // 1) LN1
    ln_kernel<<<dim3(256, BDIM), 256>>>(x, n1w, ln);
    // 2) to_hidden 1x1 (96 -> 576): M=576 -> 5 m-blocks
    gemm_tf32_kernel<false><<<dim3(512, 5, BDIM), 256>>>(w_hid, ln, nullptr, h1, C6, CDIM);
    // 3) dwconv 3x3 on 576 ch
    dwconv_kernel<<<dim3(256, C6, BDIM), 256>>>(h1, w_hdw, h2, C6);
    // 4) windowed FFT attention
    attn_kernel<<<dim3(1024, HEADS, BDIM), 256, ATTN_SMEM_FLOATS * 4>>>(h2, temp, att);
    // 5) project_out 1x1 (192 -> 96) + residual x
    gemm_tf32_kernel<true><<<dim3(512, 1, BDIM), 256>>>(w_proj, att, x, x1, CDIM, C2);
    // 6) LN2
    ln_kernel<<<dim3(256, BDIM), 256>>>(x1, n2w, ln);
    // 7) ffn in 1x1 (96 -> 510): M=510 -> 4 m-blocks
    gemm_tf32_kernel<false><<<dim3(512, 4, BDIM), 256>>>(w_fin, ln, nullptr, f1, CHID2, CDIM);
    // 8) fused dwconv 3x3 + gelu gate (510 ch -> 255 ch)
    dwgate_kernel<<<dim3(256, CHID, BDIM), 256>>>(f1, w_fdw, gg);
    // 9) ffn out 1x1 (255 -> 96) + residual x1 -> d_out
    gemm_tf32_kernel<true><<<dim3(512, 1, BDIM), 256>>>(w_fout, gg, x1, out, CDIM, CHID);
}

// round 4
// speedup vs baseline: 1.4445x; 1.1290x over previous
#include <cuda_runtime.h>
#include <math.h>
#include <stdint.h>

// ---------------- problem constants ----------------
#define IMW   256
#define HWIMG 65536          // 256*256
#define BDIM  2
#define CDIM  96
#define C6    576            // 6*DIM
#define C2    192            // 2*DIM
#define CHID  255            // hidden_features
#define CHID2 510            // 2*hidden
#define HEADS 4
#define CH    48             // channels per head (192/4)
#define NF    33             // rfft bins of 64

// ---------------- scratch (static device memory; allocation-free) ----------------
__device__ float g_ln [(size_t)BDIM * CDIM  * HWIMG];
__device__ float g_h1 [(size_t)BDIM * C6    * HWIMG];
__device__ float g_h2 [(size_t)BDIM * C6    * HWIMG];
__device__ float g_att[(size_t)BDIM * C2    * HWIMG];
__device__ float g_x1 [(size_t)BDIM * CDIM  * HWIMG];
__device__ float g_f1 [(size_t)BDIM * CHID2 * HWIMG];
__device__ float g_g  [(size_t)BDIM * CHID  * HWIMG];
__device__ uint32_t g_dft[64 * 72];   // twiddle matrix, tf32 bits

__device__ __forceinline__ uint32_t f2tf(float f) {
    uint32_t u;
    asm("cvt.rna.tf32.f32 %0, %1;" : "=r"(u) : "f"(f));
    return u;
}

__device__ __forceinline__ void mma_tf32(float* d, uint32_t a0, uint32_t a1,
                                         uint32_t a2, uint32_t a3,
                                         uint32_t b0, uint32_t b1) {
    asm volatile(
        "mma.sync.aligned.m16n8k8.row.col.f32.tf32.tf32.f32 "
        "{%0,%1,%2,%3}, {%4,%5,%6,%7}, {%8,%9}, {%0,%1,%2,%3};\n"
        : "+f"(d[0]), "+f"(d[1]), "+f"(d[2]), "+f"(d[3])
        : "r"(a0), "r"(a1), "r"(a2), "r"(a3), "r"(b0), "r"(b1));
}

// ---------------- twiddle init: D[n][2f]=cos(2pi f n/64), D[n][2f+1]=-sin ----------------
__global__ void dft_init_kernel() {
    int i = blockIdx.x * 256 + threadIdx.x;
    if (i >= 64 * 72) return;
    int n = i / 72, col = i % 72, f = col >> 1;
    float v = 0.f;
    if (col < 66) {
        float ang = 6.2831853071795864f * (float)((f * n) & 63) / 64.f;
        v = (col & 1) ? -sinf(ang) : cosf(ang);
    }
    g_dft[i] = f2tf(v);
}

// ---------------- BiasFree LayerNorm ----------------
__global__ void ln_kernel(const float* __restrict__ x, const float* __restrict__ w,
                          float* __restrict__ out) {
    int pix = blockIdx.x * 256 + threadIdx.x;
    int b   = blockIdx.y;
    const float* xb = x   + (size_t)b * CDIM * HWIMG + pix;
    float*       ob = out + (size_t)b * CDIM * HWIMG + pix;
    float s = 0.f, s2 = 0.f;
    #pragma unroll 8
    for (int c = 0; c < CDIM; c++) {
        float v = xb[(size_t)c * HWIMG];
        s += v; s2 += v * v;
    }
    float mean = s * (1.0f / CDIM);
    float var  = s2 * (1.0f / CDIM) - mean * mean;
    float inv  = rsqrtf(var + 1e-5f);
    #pragma unroll 8
    for (int c = 0; c < CDIM; c++) {
        ob[(size_t)c * HWIMG] = xb[(size_t)c * HWIMG] * inv * w[c];
    }
}

// ---------------- tf32 tensor-core conv1x1 GEMM (same as R3) ----------------
#define GBM 128
#define GBN 128
#define GBK 32
#define GPAD 8

template<bool RESID>
__global__ void __launch_bounds__(256) gemm_tf32_kernel(
        const float* __restrict__ A, const float* __restrict__ X,
        const float* __restrict__ R, float* __restrict__ Y, int M, int K) {
    __shared__ uint32_t As[GBK][GBM + GPAD];
    __shared__ uint32_t Bs[GBK][GBN + GPAD];

    int tid  = threadIdx.x;
    int warp = tid >> 5, lane = tid & 31;
    int g    = lane >> 2, tg = lane & 3;
    int wm   = (warp & 1) * 64;
    int wn   = (warp >> 1) * 32;

    int bn = blockIdx.x * GBN;
    int bm = blockIdx.y * GBM;
    int b  = blockIdx.z;
    const float* Xb = X + (size_t)b * K * HWIMG + bn;

    float acc[4][4][4];
    #pragma unroll
    for (int mt = 0; mt < 4; mt++)
        #pragma unroll
        for (int nt = 0; nt < 4; nt++)
            #pragma unroll
            for (int i = 0; i < 4; i++) acc[mt][nt][i] = 0.f;

    int xk = tid >> 3;
    int xc = (tid & 7) * 4;

    for (int k0 = 0; k0 < K; k0 += GBK) {
        #pragma unroll
        for (int i = 0; i < 16; i++) {
            int lin = tid + i * 256;
            int m = lin & 127, k = lin >> 7;
            int gm = bm + m, gk = k0 + k;
            float v = (gm < M && gk < K) ? A[(size_t)gm * K + gk] : 0.f;
            As[k][m] = f2tf(v);
        }
        {
            bool kok = (k0 + xk) < K;
            const float* p = Xb + (size_t)(k0 + xk) * HWIMG + xc;
            #pragma unroll
            for (int j = 0; j < 4; j++) {
                float4 v = kok ? *(const float4*)(p + j * 32)
                               : make_float4(0.f, 0.f, 0.f, 0.f);
                int c = xc + j * 32;
                Bs[xk][c + 0] = f2tf(v.x);
                Bs[xk][c + 1] = f2tf(v.y);
                Bs[xk][c + 2] = f2tf(v.z);
                Bs[xk][c + 3] = f2tf(v.w);
            }
        }
        __syncthreads();

        #pragma unroll
        for (int ks = 0; ks < 4; ks++) {
            int kb = ks * 8;
            uint32_t af[4][4], bf[4][2];
            #pragma unroll
            for (int mt = 0; mt < 4; mt++) {
                int m0 = wm + mt * 16;
                af[mt][0] = As[kb + tg    ][m0 + g    ];
                af[mt][1] = As[kb + tg    ][m0 + g + 8];
                af[mt][2] = As[kb + tg + 4][m0 + g    ];
                af[mt][3] = As[kb + tg + 4][m0 + g + 8];
            }
            #pragma unroll
            for (int nt = 0; nt < 4; nt++) {
                int n0 = wn + nt * 8;
                bf[nt][0] = Bs[kb + tg    ][n0 + g];
                bf[nt][1] = Bs[kb + tg + 4][n0 + g];
            }
            #pragma unroll
            for (int mt = 0; mt < 4; mt++)
                #pragma unroll
                for (int nt = 0; nt < 4; nt++)
                    mma_tf32(acc[mt][nt], af[mt][0], af[mt][1], af[mt][2], af[mt][3],
                             bf[nt][0], bf[nt][1]);
        }
        __syncthreads();
    }

    #pragma unroll
    for (int mt = 0; mt < 4; mt++) {
        int m0 = bm + wm + mt * 16 + g;
        int m1 = m0 + 8;
        #pragma unroll
        for (int nt = 0; nt < 4; nt++) {
            int n = bn + wn + nt * 8 + 2 * tg;
            if (m0 < M) {
                size_t off = ((size_t)b * M + m0) * HWIMG + n;
                float2 o = make_float2(acc[mt][nt][0], acc[mt][nt][1]);
                if (RESID) {
                    float2 r = *(const float2*)(R + off);
                    o.x += r.x; o.y += r.y;
                }
                *(float2*)(Y + off) = o;
            }
            if (m1 < M) {
                size_t off = ((size_t)b * M + m1) * HWIMG + n;
                float2 o = make_float2(acc[mt][nt][2], acc[mt][nt][3]);
                if (RESID) {
                    float2 r = *(const float2*)(R + off);
                    o.x += r.x; o.y += r.y;
                }
                *(float2*)(Y + off) = o;
            }
        }
    }
}

// ---------------- depthwise 3x3, zero padding ----------------
__device__ __forceinline__ float dw3(const float* __restrict__ ip,
                                     const float* __restrict__ wp, int y, int xx) {
    float s = 0.f;
    #pragma unroll
    for (int dy = -1; dy <= 1; dy++) {
        int yy = y + dy;
        if (yy < 0 || yy > 255) continue;
        #pragma unroll
        for (int dx = -1; dx <= 1; dx++) {
            int x2 = xx + dx;
            if (x2 < 0 || x2 > 255) continue;
            s += ip[yy * IMW + x2] * wp[(dy + 1) * 3 + (dx + 1)];
        }
    }
    return s;
}

__global__ void dwconv_kernel(const float* __restrict__ in, const float* __restrict__ w,
                              float* __restrict__ out, int C) {
    int pix = blockIdx.x * 256 + threadIdx.x;
    int c = blockIdx.y, b = blockIdx.z;
    int y = pix >> 8, xx = pix & 255;
    const float* ip = in + ((size_t)b * C + c) * HWIMG;
    out[((size_t)b * C + c) * HWIMG + pix] = dw3(ip, w + c * 9, y, xx);
}

__global__ void dwgate_kernel(const float* __restrict__ in, const float* __restrict__ w,
                              float* __restrict__ g) {
    int pix = blockIdx.x * 256 + threadIdx.x;
    int c = blockIdx.y, b = blockIdx.z;
    int y = pix >> 8, xx = pix & 255;
    const float* ip1 = in + ((size_t)b * CHID2 + c) * HWIMG;
    const float* ip2 = in + ((size_t)b * CHID2 + CHID + c) * HWIMG;
    float v1 = dw3(ip1, w + c * 9, y, xx);
    float v2 = dw3(ip2, w + (CHID + c) * 9, y, xx);
    float ge = 0.5f * v1 * (1.f + erff(v1 * 0.70710678118654752f));
    g[((size_t)b * CHID + c) * HWIMG + pix] = ge * v2;
}

// ---------------- windowed FFT attention (tensor-core DFT/irDFT) ----------------
// smem floats:
//   ASX: sxT 64x152 (tf32) -> later PT 72x56 (tf32)     [9728]
//   AD : D   64x72  (tf32)                              [4608]
//   AQF: QF 144x68 fp32 (rows: q 0-47, k 48-95, v 96-143) [9792]
//   AAT: at 33x33 float2                                [2178]
//   ANR: nrm 33
#define ASX 0
#define AD  9728
#define AQF 14336
#define AAT 24128
#define ANR 26306
#define ATTN_SMEM_FLOATS 26339

__global__ void __launch_bounds__(256, 2) attn_kernel(
        const float* __restrict__ qkv, const float* __restrict__ temp,
        float* __restrict__ outp) {
    extern __shared__ float sm[];
    uint32_t* sxT = (uint32_t*)(sm + ASX);
    uint32_t* Ds  = (uint32_t*)(sm + AD);
    float*    QF  = sm + AQF;
    float2*   at2 = (float2*)(sm + AAT);
    float*    nrm = sm + ANR;

    int tid  = threadIdx.x;
    int warp = tid >> 5, lane = tid & 31;
    int g    = lane >> 2, tg = lane & 3;
    int wy   = blockIdx.x >> 5, wx = blockIdx.x & 31;
    int head = blockIdx.y, b = blockIdx.z;

    size_t base = ((size_t)b * C6 + head * CH) * HWIMG + (size_t)(wy * 8) * IMW + wx * 8;

    // load twiddles + windows (tf32-rounded)
    for (int i = tid; i < 64 * 72; i += 256) Ds[i] = g_dft[i];
    for (int i = tid; i < 3 * CH * 64; i += 256) {
        int t = i / 3072, rem = i - t * 3072;
        int c = rem >> 6, n = rem & 63;
        float v = qkv[base + (size_t)(t * C2 + c) * HWIMG + (n >> 3) * IMW + (n & 7)];
        sxT[n * 152 + t * CH + c] = f2tf(v);
    }
    __syncthreads();

    // ---- DFT via MMA: QF(144x66) = Sx(144x64) * D(64x66) ----
    for (int mt = warp; mt < 9; mt += 8) {
        int m0 = mt * 16;
        float acc[9][4];
        #pragma unroll
        for (int nt = 0; nt < 9; nt++) {
            acc[nt][0] = acc[nt][1] = acc[nt][2] = acc[nt][3] = 0.f;
        }
        #pragma unroll
        for (int kc = 0; kc < 8; kc++) {
            int kb = kc * 8;
            uint32_t a0 = sxT[(kb + tg)     * 152 + m0 + g];
            uint32_t a1 = sxT[(kb + tg)     * 152 + m0 + g + 8];
            uint32_t a2 = sxT[(kb + tg + 4) * 152 + m0 + g];
            uint32_t a3 = sxT[(kb + tg + 4) * 152 + m0 + g + 8];
            #pragma unroll
            for (int nt = 0; nt < 9; nt++) {
                uint32_t b0 = Ds[(kb + tg)     * 72 + nt * 8 + g];
                uint32_t b1 = Ds[(kb + tg + 4) * 72 + nt * 8 + g];
                mma_tf32(acc[nt], a0, a1, a2, a3, b0, b1);
            }
        }
        #pragma unroll
        for (int nt = 0; nt < 9; nt++) {
            int col = nt * 8 + 2 * tg;
            if (col < 66) {
                *(float2*)&QF[(m0 + g)     * 68 + col] = make_float2(acc[nt][0], acc[nt][1]);
                *(float2*)&QF[(m0 + g + 8) * 68 + col] = make_float2(acc[nt][2], acc[nt][3]);
            }
        }
    }
    __syncthreads();

    // ---- gram: at[f][g] = tv * sum_c qf[c][f]*kf[c][g] (complex) ----
    float tv = temp[head];
    const float2* qf2 = (const float2*)QF;   // stride 34 float2 per row
    for (int e = tid; e < 17 * 17; e += 256) {
        int ft = e / 17, gt = e - ft * 17;
        int f0 = ft * 2, g0 = gt * 2;
        int f1 = (f0 + 1 < NF) ? f0 + 1 : f0;
        int g1 = (g0 + 1 < NF) ? g0 + 1 : g0;
        float2 a00 = {0,0}, a01 = {0,0}, a10 = {0,0}, a11 = {0,0};
        #pragma unroll 4
        for (int c = 0; c < CH; c++) {
            float2 q0 = qf2[c * 34 + f0], q1 = qf2[c * 34 + f1];
            float2 k0 = qf2[(CH + c) * 34 + g0], k1 = qf2[(CH + c) * 34 + g1];
            a00.x += q0.x*k0.x - q0.y*k0.y; a00.y += q0.x*k0.y + q0.y*k0.x;
            a01.x += q0.x*k1.x - q0.y*k1.y; a01.y += q0.x*k1.y + q0.y*k1.x;
            a10.x += q1.x*k0.x - q1.y*k0.y; a10.y += q1.x*k0.y + q1.y*k0.x;
            a11.x += q1.x*k1.x - q1.y*k1.y; a11.y += q1.x*k1.y + q1.y*k1.x;
        }
        at2[f0 * NF + g0] = make_float2(a00.x * tv, a00.y * tv);
        if (g0 + 1 < NF) at2[f0 * NF + g0 + 1] = make_float2(a01.x * tv, a01.y * tv);
        if (f0 + 1 < NF) {
            at2[(f0 + 1) * NF + g0] = make_float2(a10.x * tv, a10.y * tv);
            if (g0 + 1 < NF) at2[(f0 + 1) * NF + g0 + 1] = make_float2(a11.x * tv, a11.y * tv);
        }
    }
    __syncthreads();

    // ---- row norms + zero PT pad rows (sxT region now dead) ----
    uint32_t* PT = sxT;     // 72 rows x 56 cols (tf32)
    if (tid < NF) {
        float s = 0.f;
        #pragma unroll
        for (int gg = 0; gg < NF; gg++) {
            float2 a = at2[tid * NF + gg];
            s += a.x * a.x + a.y * a.y;
        }
        nrm[tid] = rsqrtf(s);
    }
    for (int i = tid; i < 6 * 56; i += 256) PT[66 * 56 + i] = 0u;
    __syncthreads();

    // ---- apply: P[c][f] = nrm[f]*wf/64 * sum_g at[f][g]*vf[c][g]; write PT[fc][c] ----
    // lanes span channels (cg) so PT stores are conflict-free
    if (tid < 204) {
        int cg = tid % 12, fg = tid / 12;     // fg 0..16, cg 0..11
        int c0 = cg * 4, f0 = fg * 2;
        bool has1 = (f0 + 1) < NF;
        int f1 = has1 ? f0 + 1 : f0;
        float2 acc0[4] = {{0,0},{0,0},{0,0},{0,0}};
        float2 acc1[4] = {{0,0},{0,0},{0,0},{0,0}};
        #pragma unroll 3
        for (int gg = 0; gg < NF; gg++) {
            float2 a0 = at2[f0 * NF + gg], a1 = at2[f1 * NF + gg];
            #pragma unroll
            for (int j = 0; j < 4; j++) {
                float2 v = qf2[(2 * CH + c0 + j) * 34 + gg];
                acc0[j].x += a0.x*v.x - a0.y*v.y; acc0[j].y += a0.x*v.y + a0.y*v.x;
                acc1[j].x += a1.x*v.x - a1.y*v.y; acc1[j].y += a1.x*v.y + a1.y*v.x;
            }
        }
        float s0 = nrm[f0] * ((f0 == 0 || f0 == 32) ? 1.f : 2.f) * (1.f / 64.f);
        float s1 = nrm[f1] * 2.f * (1.f / 64.f);
        #pragma unroll
        for (int j = 0; j < 4; j++) {
            PT[(2 * f0)     * 56 + c0 + j] = f2tf(acc0[j].x * s0);
            PT[(2 * f0 + 1) * 56 + c0 + j] = f2tf(acc0[j].y * s0);
            if (has1) {
                PT[(2 * f1)     * 56 + c0 + j] = f2tf(acc1[j].x * s1);
                PT[(2 * f1 + 1) * 56 + c0 + j] = f2tf(acc1[j].y * s1);
            }
        }
    }
    __syncthreads();

    // ---- irDFT via MMA: out(48x64) = P(48x66) * D^T (re*cos - im*sin, wf/64 folded) ----
    float* outBase = outp + ((size_t)b * C2 + head * CH) * HWIMG
                   + (size_t)(wy * 8) * IMW + wx * 8;
    for (int t = warp; t < 24; t += 8) {
        int mt = t / 8, nt = t % 8;
        int m0 = mt * 16, n0 = nt * 8;
        float acc[4] = {0.f, 0.f, 0.f, 0.f};
        #pragma unroll
        for (int kc = 0; kc < 9; kc++) {
            int kb = kc * 8;
            uint32_t a0 = PT[(kb + tg)     * 56 + m0 + g];
            uint32_t a1 = PT[(kb + tg)     * 56 + m0 + g + 8];
            uint32_t a2 = PT[(kb + tg + 4) * 56 + m0 + g];
            uint32_t a3 = PT[(kb + tg + 4) * 56 + m0 + g + 8];
            uint32_t b0 = Ds[(n0 + g) * 72 + kb + tg];
            uint32_t b1 = Ds[(n0 + g) * 72 + kb + tg + 4];
            mma_tf32(acc, a0, a1, a2, a3, b0, b1);
        }
        int c = m0 + g;
        *(float2*)&outBase[(size_t)c       * HWIMG + nt * IMW + 2 * tg] =
            make_float2(acc[0], acc[1]);
        *(float2*)&outBase[(size_t)(c + 8) * HWIMG + nt * IMW + 2 * tg] =
            make_float2(acc[2], acc[3]);
    }
}

// ---------------- launch ----------------
extern "C" void kernel_launch(void* const* d_in, const int* in_sizes, int n_in,
                              void* d_out, int out_size) {
    const float* x      = (const float*)d_in[0];
    const float* w_hid  = (const float*)d_in[1];
    const float* w_hdw  = (const float*)d_in[2];
    const float* w_proj = (const float*)d_in[3];
    const float* temp   = (const float*)d_in[4];
    const float* n1w    = (const float*)d_in[5];
    const float* n2w    = (const float*)d_in[6];
    const float* w_fin  = (const float*)d_in[7];
    const float* w_fdw  = (const float*)d_in[8];
    const float* w_fout = (const float*)d_in[9];
    float* out = (float*)d_out;

    float *ln, *h1, *h2, *att, *x1, *f1, *gg;
    cudaGetSymbolAddress((void**)&ln,  g_ln);
    cudaGetSymbolAddress((void**)&h1,  g_h1);
    cudaGetSymbolAddress((void**)&h2,  g_h2);
    cudaGetSymbolAddress((void**)&att, g_att);
    cudaGetSymbolAddress((void**)&x1,  g_x1);
    cudaGetSymbolAddress((void**)&f1,  g_f1);
    cudaGetSymbolAddress((void**)&gg,  g_g);

    cudaFuncSetAttribute(attn_kernel, cudaFuncAttributeMaxDynamicSharedMemorySize,
                         ATTN_SMEM_FLOATS * 4);

    // 0) twiddle matrix init
    dft_init_kernel<<<18, 256>>>();
    // 1) LN1
    ln_kernel<<<dim3(256, BDIM), 256>>>(x, n1w, ln);
    // 2) to_hidden 1x1 (96 -> 576)
    gemm_tf32_kernel<false><<<dim3(512, 5, BDIM), 256>>>(w_hid, ln, nullptr, h1, C6, CDIM);
    // 3) dwconv 3x3 on 576 ch
    dwconv_kernel<<<dim3(256, C6, BDIM), 256>>>(h1, w_hdw, h2, C6);
    // 4) windowed FFT attention (tensor-core DFT/irDFT)
    attn_kernel<<<dim3(1024, HEADS, BDIM), 256, ATTN_SMEM_FLOATS * 4>>>(h2, temp, att);
    // 5) project_out 1x1 (192 -> 96) + residual x
    gemm_tf32_kernel<true><<<dim3(512, 1, BDIM), 256>>>(w_proj, att, x, x1, CDIM, C2);
    // 6) LN2
    ln_kernel<<<dim3(256, BDIM), 256>>>(x1, n2w, ln);
    // 7) ffn in 1x1 (96 -> 510)
    gemm_tf32_kernel<false><<<dim3(512, 4, BDIM), 256>>>(w_fin, ln, nullptr, f1, CHID2, CDIM);
    // 8) fused dwconv 3x3 + gelu gate (510 ch -> 255 ch)
    dwgate_kernel<<<dim3(256, CHID, BDIM), 256>>>(f1, w_fdw, gg);
    // 9) ffn out 1x1 (255 -> 96) + residual x1 -> d_out
    gemm_tf32_kernel<true><<<dim3(512, 1, BDIM), 256>>>(w_fout, gg, x1, out, CDIM, CHID);
}